// round 14
// baseline (speedup 1.0000x reference)
#include <cuda_runtime.h>
#include <math.h>

#define Bsz 32768
#define Lsz 2048
#define NGc 4
#define GLc 64
#define NTHREADS 256
#define BPT 32                 // batches per tile (= 4 rows per warp)
#define NTILES (Bsz/BPT)       // 1024
#define GRID 296               // 148 SMs x 2 CTAs

typedef unsigned long long ull;

// weight scratch, packed/transposed once by prep_kernel (48KB total — fits L1D; do NOT grow)
__device__ float4 w12G[64][32];   // [k][jp] = {W1[2jp][k],W1[2jp+1][k],W2[2jp][k],W2[2jp+1][k]}
__device__ float2 waG[64][32];    // [k][jp] = {Wa[2jp][k],Wa[2jp+1][k]}

#define PSTRIDE 66             // pairs-dim stride (64 + pad)

struct __align__(16) Smem {
    ull xmPair[64][PSTRIDE];   // [k][p] = pack(xm row 2p, row 2p+1); warp w owns p = 8w..8w+7
    ull lsumPair[64][PSTRIDE]; // [k][p] = pack(lsum[2p][k], lsum[2p+1][k]); warp-private likewise
    int   idxS[256];
    int2  sortS[256];          // {gather index (ascending), xmPair byte offset}
    float bl1s[64], bl2s[64], bas[64];
    float w1n[3]; float b1s;
    float w2n[4][12]; float b2s[4];
};

__device__ __forceinline__ ull pk2(float lo, float hi) {
    ull r; asm("mov.b64 %0,{%1,%2};" : "=l"(r) : "f"(lo), "f"(hi)); return r;
}
__device__ __forceinline__ float2 up2(ull v) {
    float2 r; asm("mov.b64 {%0,%1},%2;" : "=f"(r.x), "=f"(r.y) : "l"(v)); return r;
}
__device__ __forceinline__ void fma2(ull& d, ull a, ull b) {
    asm("fma.rn.f32x2 %0,%1,%2,%0;" : "+l"(d) : "l"(a), "l"(b));
}
__device__ __forceinline__ float tanha(float x) {
    float r; asm("tanh.approx.f32 %0,%1;" : "=f"(r) : "f"(x)); return r;
}
__device__ __forceinline__ float tanh2(float x) { return tanha(tanha(x)); }
__device__ __forceinline__ float sigmoidf(float z) {
    return fmaf(0.5f, tanha(0.5f*z), 0.5f);
}

__global__ void prep_kernel(const float* __restrict__ W1, const float* __restrict__ W2,
                            const float* __restrict__ Wa)
{
    int p = blockIdx.x * blockDim.x + threadIdx.x;
    if (p < 2048) {
        int k = p >> 5, jp = p & 31;
        w12G[k][jp] = make_float4(W1[(2*jp)*64 + k], W1[(2*jp+1)*64 + k],
                                  W2[(2*jp)*64 + k], W2[(2*jp+1)*64 + k]);
        waG[k][jp]  = make_float2(Wa[(2*jp)*64 + k], Wa[(2*jp+1)*64 + k]);
    }
}

// conv1 + double-tanh over TWO full rows as one 16-chunk pipeline, warp-private.
// default-cached loads (warm L2 for the gather), __stcs stores (never re-read).
__device__ __forceinline__ void stream_rows2(const float4* __restrict__ xr0,
                                             const float4* __restrict__ xr1,
                                             float* __restrict__ so0,
                                             float* __restrict__ so1, int lane,
                                             float cw0, float cw1, float cw2, float cb)
{
    float4 A[4], B[4];
    A[0] = xr0[2*lane];        B[0] = xr0[2*lane+1];
    A[1] = xr0[64 + 2*lane];   B[1] = xr0[64 + 2*lane+1];
    A[2] = xr0[128 + 2*lane];  B[2] = xr0[128 + 2*lane+1];
    float prev_last = 0.f;
    #pragma unroll
    for (int cc = 0; cc < 16; cc++) {
        const int cur = cc & 3, nx = (cc+1) & 3, ld = (cc+3) & 3;
        if (cc < 13) {
            const int tc = cc + 3;
            const float4* base = (tc < 8) ? xr0 : xr1;
            const int off = (tc & 7) * 64;
            A[ld] = base[off + 2*lane];
            B[ld] = base[off + 2*lane + 1];
        }
        const int c = cc & 7;
        float4 ra = A[cur], rb = B[cur];
        float nextfirst = (cc < 15) ? __shfl_sync(0xffffffffu, A[nx].x, 0) : 0.f;
        float em1 = __shfl_up_sync(0xffffffffu,  rb.w, 1);
        float ep8 = __shfl_down_sync(0xffffffffu, ra.x, 1);
        if (lane == 0)  em1 = (c == 0) ? 0.f : prev_last;
        if (lane == 31) ep8 = (c == 7) ? 0.f : nextfirst;
        prev_last = __shfl_sync(0xffffffffu, rb.w, 31);
        float e[10] = {em1, ra.x, ra.y, ra.z, ra.w, rb.x, rb.y, rb.z, rb.w, ep8};
        float r[8];
        #pragma unroll
        for (int q = 0; q < 8; q++)
            r[q] = tanh2(fmaf(cw0, e[q], fmaf(cw1, e[q+1], fmaf(cw2, e[q+2], cb))));
        float* so = (cc < 8) ? so0 : so1;
        float* o = so + c*256 + lane*8;
        __stcs((float4*)o,     make_float4(r[0], r[1], r[2], r[3]));
        __stcs((float4*)(o+4), make_float4(r[4], r[5], r[6], r[7]));
    }
}

__global__ void __launch_bounds__(NTHREADS, 2)
fused_kernel(const float* __restrict__ x, const int* __restrict__ index_all,
             const float* __restrict__ v1, const float* __restrict__ g1, const float* __restrict__ b1,
             const float* __restrict__ v2, const float* __restrict__ g2, const float* __restrict__ b2,
             const float* __restrict__ bl1, const float* __restrict__ bl2,
             const float* __restrict__ ba,
             float* __restrict__ out)
{
    __shared__ Smem sm;
    Smem* s = &sm;
    const int t = threadIdx.x;
    const int lane = t & 31;
    const int w = t >> 5;          // warp id: owns batch rows 4w..4w+3 of each tile

    // ---------------- init ----------------
    s->idxS[t] = index_all[t];
    if (t < 64) {
        s->bl1s[t] = bl1[t];
        s->bl2s[t] = bl2[t];
        s->bas[t]  = ba[t];
    }
    if (t == 0) {
        float n = sqrtf(v1[0]*v1[0] + v1[1]*v1[1] + v1[2]*v1[2]);
        float gg = g1[0] / n;
        s->w1n[0] = gg*v1[0]; s->w1n[1] = gg*v1[1]; s->w1n[2] = gg*v1[2];
        s->b1s = b1[0];
    }
    if (t < 4) {
        float ss = 0.f;
        #pragma unroll
        for (int m = 0; m < 12; m++) { float vv = v2[t*12+m]; ss += vv*vv; }
        float gg = g2[t] / sqrtf(ss);
        #pragma unroll
        for (int m = 0; m < 12; m++) s->w2n[t][m] = gg * v2[t*12+m];
        s->b2s[t] = b2[t];
    }
    __syncthreads();

    // rank-sort gather indices (stable); precompute scatter byte-offsets
    {
        const int v = s->idxS[t];
        int rank = 0;
        #pragma unroll 8
        for (int j = 0; j < 256; j++) {
            int u = s->idxS[j];
            rank += (u < v) || (u == v && j < t);
        }
        const int k = t & 63, g = t >> 6;
        // base byte offset within xmPair for (k, gh=g>>1, e=g&1); add sbl*16 at use
        s->sortS[rank] = make_int2(v, k*(PSTRIDE*8) + (g >> 1)*8 + (g & 1)*4);
    }
    __syncthreads();

    const float cw0 = s->w1n[0], cw1 = s->w1n[1], cw2 = s->w1n[2], cb = s->b1s;
    // MLP mapping: column pair j0=2jp; row-pairs rp0..rp0+7 (16 rows = 4 batches x 4 g)
    const int jp = lane, j0 = 2*jp;
    const int rp0 = w * 8;
    const float bias1 = s->bl1s[j0],   bias1b = s->bl1s[j0+1];
    const float bias2 = s->bl2s[j0],   bias2b = s->bl2s[j0+1];
    const float biasA = s->bas[j0],    biasAb = s->bas[j0+1];

    float* out_bag  = out;
    float* out_site = out + (size_t)Bsz * NGc * GLc;
    char* xmBase = (char*)&s->xmPair[0][0];

    // per-tile state is warp-private -> no CTA barriers in the tile loop
    for (int tile = blockIdx.x; tile < NTILES; tile += GRID) {
        const int b0 = tile * BPT;
        const int sb = 4*w;          // first of this warp's 4 batch rows

        // ---- stream 4 warp-private rows: conv1 -> x_site (warms L2) ----
        stream_rows2((const float4*)(x + (size_t)(b0 + sb) * Lsz),
                     (const float4*)(x + (size_t)(b0 + sb + 1) * Lsz),
                     out_site + (size_t)(b0 + sb) * Lsz,
                     out_site + (size_t)(b0 + sb + 1) * Lsz,
                     lane, cw0, cw1, cw2, cb);
        stream_rows2((const float4*)(x + (size_t)(b0 + sb + 2) * Lsz),
                     (const float4*)(x + (size_t)(b0 + sb + 3) * Lsz),
                     out_site + (size_t)(b0 + sb + 2) * Lsz,
                     out_site + (size_t)(b0 + sb + 3) * Lsz,
                     lane, cw0, cw1, cw2, cb);

        // ---- gather xm for 4 rows AFTER stream (L2-hot), sorted order ----
        {
            const float* xq0 = x + (size_t)(b0 + sb)     * Lsz;
            const float* xq1 = x + (size_t)(b0 + sb + 1) * Lsz;
            const float* xq2 = x + (size_t)(b0 + sb + 2) * Lsz;
            const float* xq3 = x + (size_t)(b0 + sb + 3) * Lsz;
            float va[8], vb[8], vc[8], vd[8];
            #pragma unroll
            for (int c = 0; c < 8; c++) {
                const int gi = s->sortS[c*32 + lane].x;
                va[c] = __ldg(xq0 + gi);
                vb[c] = __ldg(xq1 + gi);
                vc[c] = __ldg(xq2 + gi);
                vd[c] = __ldg(xq3 + gi);
            }
            #pragma unroll
            for (int c = 0; c < 8; c++) {
                const int off = s->sortS[c*32 + lane].y;
                char* p = xmBase + off + sb*16;
                *(float*)(p)      = va[c];
                *(float*)(p + 16) = vb[c];
                *(float*)(p + 32) = vc[c];
                *(float*)(p + 48) = vd[c];
            }
        }
        __syncwarp();

        // ---- phase 1: lsum = relu(xm@W1^T+bl1) + relu(xm@W2^T+bl2), 8 pairs ----
        ull a1a[8], a1b[8], a2a[8], a2b[8];
        #pragma unroll
        for (int i = 0; i < 8; i++) {
            a1a[i] = pk2(bias1, bias1);  a1b[i] = pk2(bias1b, bias1b);
            a2a[i] = pk2(bias2, bias2);  a2b[i] = pk2(bias2b, bias2b);
        }
        #pragma unroll 2
        for (int k = 0; k < 64; k++) {
            const float4 wv = w12G[k][jp];          // LDG.128, L1-resident (amortized 16 rows)
            ull w1a = pk2(wv.x, wv.x), w1b = pk2(wv.y, wv.y);
            ull w2a = pk2(wv.z, wv.z), w2b = pk2(wv.w, wv.w);
            #pragma unroll
            for (int h = 0; h < 4; h++) {
                ulonglong2 A = *(const ulonglong2*)&s->xmPair[k][rp0 + 2*h];
                fma2(a1a[2*h],   A.x, w1a); fma2(a1b[2*h],   A.x, w1b);
                fma2(a2a[2*h],   A.x, w2a); fma2(a2b[2*h],   A.x, w2b);
                fma2(a1a[2*h+1], A.y, w1a); fma2(a1b[2*h+1], A.y, w1b);
                fma2(a2a[2*h+1], A.y, w2a); fma2(a2b[2*h+1], A.y, w2b);
            }
        }
        {   // relu+sum, vectorized STS.128 (4 per column row)
            #pragma unroll
            for (int h = 0; h < 4; h++) {
                ulonglong2 sA, sB;
                float2 u0 = up2(a1a[2*h]),   v0 = up2(a2a[2*h]);
                float2 u1 = up2(a1a[2*h+1]), v1u = up2(a2a[2*h+1]);
                sA.x = pk2(fmaxf(u0.x,0.f)+fmaxf(v0.x,0.f), fmaxf(u0.y,0.f)+fmaxf(v0.y,0.f));
                sA.y = pk2(fmaxf(u1.x,0.f)+fmaxf(v1u.x,0.f), fmaxf(u1.y,0.f)+fmaxf(v1u.y,0.f));
                float2 w0 = up2(a1b[2*h]),   x0 = up2(a2b[2*h]);
                float2 w1 = up2(a1b[2*h+1]), x1 = up2(a2b[2*h+1]);
                sB.x = pk2(fmaxf(w0.x,0.f)+fmaxf(x0.x,0.f), fmaxf(w0.y,0.f)+fmaxf(x0.y,0.f));
                sB.y = pk2(fmaxf(w1.x,0.f)+fmaxf(x1.x,0.f), fmaxf(w1.y,0.f)+fmaxf(x1.y,0.f));
                *(ulonglong2*)&s->lsumPair[j0][rp0 + 2*h]   = sA;
                *(ulonglong2*)&s->lsumPair[j0+1][rp0 + 2*h] = sB;
            }
        }
        __syncwarp();

        // ---- phase 2: A = sigmoid(lsum@Wa^T+ba), 8 pairs ----
        ull aA0[8], aA1[8];
        #pragma unroll
        for (int i = 0; i < 8; i++) { aA0[i] = pk2(biasA, biasA); aA1[i] = pk2(biasAb, biasAb); }
        #pragma unroll 2
        for (int k = 0; k < 64; k++) {
            const float2 wv = waG[k][jp];           // LDG.64, L1-resident
            ull wa0 = pk2(wv.x, wv.x), wa1 = pk2(wv.y, wv.y);
            #pragma unroll
            for (int h = 0; h < 4; h++) {
                ulonglong2 A = *(const ulonglong2*)&s->lsumPair[k][rp0 + 2*h];
                fma2(aA0[2*h],   A.x, wa0); fma2(aA1[2*h],   A.x, wa1);
                fma2(aA0[2*h+1], A.y, wa0); fma2(aA1[2*h+1], A.y, wa1);
            }
        }

        // ---- epilogue per batch: xmask, lane-shuffle halo, conv2, store ----
        #pragma unroll
        for (int bb = 0; bb < 4; bb++) {
            float xmv[2][2][2];   // [i][e][c]: pairs i0=2bb+i, elem e, col j0+c
            #pragma unroll
            for (int i = 0; i < 2; i++) {
                const int pi = 2*bb + i;
                float2 z0 = up2(aA0[pi]), z1 = up2(aA1[pi]);
                float2 x0 = up2(s->xmPair[j0][rp0 + pi]);
                float2 x1 = up2(s->xmPair[j0+1][rp0 + pi]);
                xmv[i][0][0] = (sigmoidf(z0.x)+1.f)*x0.x;
                xmv[i][1][0] = (sigmoidf(z0.y)+1.f)*x0.y;
                xmv[i][0][1] = (sigmoidf(z1.x)+1.f)*x1.x;
                xmv[i][1][1] = (sigmoidf(z1.y)+1.f)*x1.y;
            }
            float lf[2][2], rt[2][2];
            #pragma unroll
            for (int i = 0; i < 2; i++) {
                #pragma unroll
                for (int e = 0; e < 2; e++) {
                    float l = __shfl_up_sync(0xffffffffu,  xmv[i][e][1], 1);
                    float r = __shfl_down_sync(0xffffffffu, xmv[i][e][0], 1);
                    lf[i][e] = (jp == 0)  ? 0.f : l;
                    rt[i][e] = (jp == 31) ? 0.f : r;
                }
            }
            #pragma unroll
            for (int oo = 0; oo < 4; oo++) {
                float4 wA = *(const float4*)&s->w2n[oo][0];
                float4 wB = *(const float4*)&s->w2n[oo][4];
                float4 wC = *(const float4*)&s->w2n[oo][8];
                const float wv[12] = {wA.x,wA.y,wA.z,wA.w, wB.x,wB.y,wB.z,wB.w,
                                      wC.x,wC.y,wC.z,wC.w};
                float a0 = s->b2s[oo], a1 = a0;
                #pragma unroll
                for (int g = 0; g < 4; g++) {
                    const int i = g >> 1, e = g & 1;
                    const float xl = lf[i][e], xa = xmv[i][e][0],
                                xb = xmv[i][e][1], xr = rt[i][e];
                    a0 = fmaf(wv[3*g],   xl, a0);
                    a0 = fmaf(wv[3*g+1], xa, a0);
                    a0 = fmaf(wv[3*g+2], xb, a0);
                    a1 = fmaf(wv[3*g],   xa, a1);
                    a1 = fmaf(wv[3*g+1], xb, a1);
                    a1 = fmaf(wv[3*g+2], xr, a1);
                }
                __stcs((float2*)&out_bag[(size_t)(b0 + sb + bb) * (NGc*GLc) + oo*GLc + j0],
                       make_float2(tanh2(a0), tanh2(a1)));
            }
        }
        __syncwarp();   // order phase-2 xmPair reads before next tile's gather writes
    }
}

extern "C" void kernel_launch(void* const* d_in, const int* in_sizes, int n_in,
                              void* d_out, int out_size)
{
    const float* x   = (const float*)d_in[0];
    const int*   idx = (const int*)  d_in[1];
    const float* v1  = (const float*)d_in[2];
    const float* g1  = (const float*)d_in[3];
    const float* b1  = (const float*)d_in[4];
    const float* v2  = (const float*)d_in[5];
    const float* g2  = (const float*)d_in[6];
    const float* b2  = (const float*)d_in[7];
    const float* W1  = (const float*)d_in[8];
    const float* bl1 = (const float*)d_in[9];
    const float* W2  = (const float*)d_in[10];
    const float* bl2 = (const float*)d_in[11];
    const float* Wa  = (const float*)d_in[12];
    const float* ba  = (const float*)d_in[13];

    prep_kernel<<<8, 256>>>(W1, W2, Wa);
    fused_kernel<<<GRID, NTHREADS>>>(
        x, idx, v1, g1, b1, v2, g2, b2, bl1, bl2, ba, (float*)d_out);
}

// round 15
// speedup vs baseline: 1.4302x; 1.4302x over previous
#include <cuda_runtime.h>
#include <math.h>

#define Bsz 32768
#define Lsz 2048
#define NGc 4
#define GLc 64
#define NTHREADS 256
#define BPT 16                 // batches per tile (= 2 rows per warp)
#define NTILES (Bsz/BPT)       // 2048
#define GRID 444               // 148 SMs x 3 CTAs

typedef unsigned long long ull;

// weight scratch, packed/transposed once by prep_kernel (48KB total — fits L1D; do NOT grow)
__device__ float4 w12G[64][32];   // [k][jp] = {W1[2jp][k],W1[2jp+1][k],W2[2jp][k],W2[2jp+1][k]}
__device__ float2 waG[64][32];    // [k][jp] = {Wa[2jp][k],Wa[2jp+1][k]}

struct __align__(16) Smem {
    ull xmPair[64][34];       // [k][p] = pack(xm of row 2p, row 2p+1); warp w owns p = 4w..4w+3
    ull lsumPair[64][34];     // [k][p] = pack(lsum[2p][k], lsum[2p+1][k]); warp-private likewise
    int   idxS[256];
    int2  sortS[256];         // {gather index (ascending), xmPair byte offset}
    float bl1s[64], bl2s[64], bas[64];
    float w1n[3]; float b1s;
    float w2n[4][12]; float b2s[4];
};

__device__ __forceinline__ ull pk2(float lo, float hi) {
    ull r; asm("mov.b64 %0,{%1,%2};" : "=l"(r) : "f"(lo), "f"(hi)); return r;
}
__device__ __forceinline__ float2 up2(ull v) {
    float2 r; asm("mov.b64 {%0,%1},%2;" : "=f"(r.x), "=f"(r.y) : "l"(v)); return r;
}
__device__ __forceinline__ void fma2(ull& d, ull a, ull b) {
    asm("fma.rn.f32x2 %0,%1,%2,%0;" : "+l"(d) : "l"(a), "l"(b));
}
__device__ __forceinline__ float tanha(float x) {
    float r; asm("tanh.approx.f32 %0,%1;" : "=f"(r) : "f"(x)); return r;
}
__device__ __forceinline__ float tanh2(float x) { return tanha(tanha(x)); }
// sigmoid(z) = 0.5 + 0.5*tanh(z/2): 1 MUFU + 2 FMA (validated rel_err)
__device__ __forceinline__ float sigmoidf(float z) {
    return fmaf(0.5f, tanha(0.5f*z), 0.5f);
}

__global__ void prep_kernel(const float* __restrict__ W1, const float* __restrict__ W2,
                            const float* __restrict__ Wa)
{
    int p = blockIdx.x * blockDim.x + threadIdx.x;
    if (p < 2048) {
        int k = p >> 5, jp = p & 31;
        w12G[k][jp] = make_float4(W1[(2*jp)*64 + k], W1[(2*jp+1)*64 + k],
                                  W2[(2*jp)*64 + k], W2[(2*jp+1)*64 + k]);
        waG[k][jp]  = make_float2(Wa[(2*jp)*64 + k], Wa[(2*jp+1)*64 + k]);
    }
}

// conv1 + double-tanh over TWO full rows as one 16-chunk pipeline, warp-private,
// barrier-free. 4-deep rotating buffer = 3-chunk prefetch; no cold restart at
// the row boundary. Loads DEFAULT-cached (they warm L2 for the gather!);
// stores __stcs (outputs never re-read -> evict-first, preserve L2 for x rows).
__device__ __forceinline__ void stream_rows2(const float4* __restrict__ xr0,
                                             const float4* __restrict__ xr1,
                                             float* __restrict__ so0,
                                             float* __restrict__ so1, int lane,
                                             float cw0, float cw1, float cw2, float cb)
{
    float4 A[4], B[4];
    A[0] = xr0[2*lane];        B[0] = xr0[2*lane+1];
    A[1] = xr0[64 + 2*lane];   B[1] = xr0[64 + 2*lane+1];
    A[2] = xr0[128 + 2*lane];  B[2] = xr0[128 + 2*lane+1];
    float prev_last = 0.f;
    #pragma unroll
    for (int cc = 0; cc < 16; cc++) {
        const int cur = cc & 3, nx = (cc+1) & 3, ld = (cc+3) & 3;
        if (cc < 13) {
            const int tc = cc + 3;
            const float4* base = (tc < 8) ? xr0 : xr1;
            const int off = (tc & 7) * 64;
            A[ld] = base[off + 2*lane];
            B[ld] = base[off + 2*lane + 1];
        }
        const int c = cc & 7;
        float4 ra = A[cur], rb = B[cur];
        float nextfirst = (cc < 15) ? __shfl_sync(0xffffffffu, A[nx].x, 0) : 0.f;
        float em1 = __shfl_up_sync(0xffffffffu,  rb.w, 1);
        float ep8 = __shfl_down_sync(0xffffffffu, ra.x, 1);
        if (lane == 0)  em1 = (c == 0) ? 0.f : prev_last;
        if (lane == 31) ep8 = (c == 7) ? 0.f : nextfirst;
        prev_last = __shfl_sync(0xffffffffu, rb.w, 31);
        float e[10] = {em1, ra.x, ra.y, ra.z, ra.w, rb.x, rb.y, rb.z, rb.w, ep8};
        float r[8];
        #pragma unroll
        for (int q = 0; q < 8; q++)
            r[q] = tanh2(fmaf(cw0, e[q], fmaf(cw1, e[q+1], fmaf(cw2, e[q+2], cb))));
        float* so = (cc < 8) ? so0 : so1;
        float* o = so + c*256 + lane*8;
        __stcs((float4*)o,     make_float4(r[0], r[1], r[2], r[3]));
        __stcs((float4*)(o+4), make_float4(r[4], r[5], r[6], r[7]));
    }
}

__global__ void __launch_bounds__(NTHREADS, 3)
fused_kernel(const float* __restrict__ x, const int* __restrict__ index_all,
             const float* __restrict__ v1, const float* __restrict__ g1, const float* __restrict__ b1,
             const float* __restrict__ v2, const float* __restrict__ g2, const float* __restrict__ b2,
             const float* __restrict__ bl1, const float* __restrict__ bl2,
             const float* __restrict__ ba,
             float* __restrict__ out)
{
    __shared__ Smem sm;
    Smem* s = &sm;
    const int t = threadIdx.x;
    const int lane = t & 31;
    const int w = t >> 5;          // warp id: owns batch rows 2w, 2w+1 of each tile

    // ---------------- init ----------------
    s->idxS[t] = index_all[t];
    if (t < 64) {
        s->bl1s[t] = bl1[t];
        s->bl2s[t] = bl2[t];
        s->bas[t]  = ba[t];
    }
    if (t == 0) {
        float n = sqrtf(v1[0]*v1[0] + v1[1]*v1[1] + v1[2]*v1[2]);
        float gg = g1[0] / n;
        s->w1n[0] = gg*v1[0]; s->w1n[1] = gg*v1[1]; s->w1n[2] = gg*v1[2];
        s->b1s = b1[0];
    }
    if (t < 4) {
        float ss = 0.f;
        #pragma unroll
        for (int m = 0; m < 12; m++) { float vv = v2[t*12+m]; ss += vv*vv; }
        float gg = g2[t] / sqrtf(ss);
        #pragma unroll
        for (int m = 0; m < 12; m++) s->w2n[t][m] = gg * v2[t*12+m];
        s->b2s[t] = b2[t];
    }
    __syncthreads();

    // rank-sort gather indices (stable); precompute scatter byte-offsets
    {
        const int v = s->idxS[t];
        int rank = 0;
        #pragma unroll 8
        for (int j = 0; j < 256; j++) {
            int u = s->idxS[j];
            rank += (u < v) || (u == v && j < t);
        }
        const int k = t & 63, g = t >> 6;
        s->sortS[rank] = make_int2(v, k*272 + (g >> 1)*8 + (g & 1)*4);
    }
    __syncthreads();

    const float cw0 = s->w1n[0], cw1 = s->w1n[1], cw2 = s->w1n[2], cb = s->b1s;
    // MLP mapping: column pair j0=2jp, row-pairs rp0..rp0+3 (8 rows = 2 batches x 4 g)
    const int jp = lane, j0 = 2*jp;
    const int rp0 = w * 4;
    const float bias1 = s->bl1s[j0],   bias1b = s->bl1s[j0+1];
    const float bias2 = s->bl2s[j0],   bias2b = s->bl2s[j0+1];
    const float biasA = s->bas[j0],    biasAb = s->bas[j0+1];

    float* out_bag  = out;
    float* out_site = out + (size_t)Bsz * NGc * GLc;
    char* xmBase = (char*)&s->xmPair[0][0];

    // per-tile state is warp-private -> no CTA barriers in the tile loop
    for (int tile = blockIdx.x; tile < NTILES; tile += GRID) {
        const int b0 = tile * BPT;
        const int sbl0 = 2*w, sbl1 = 2*w + 1;

        // ---- stream 2 warp-private rows (one fused pipeline): conv1 -> x_site ----
        stream_rows2((const float4*)(x + (size_t)(b0 + sbl0) * Lsz),
                     (const float4*)(x + (size_t)(b0 + sbl1) * Lsz),
                     out_site + (size_t)(b0 + sbl0) * Lsz,
                     out_site + (size_t)(b0 + sbl1) * Lsz,
                     lane, cw0, cw1, cw2, cb);

        // ---- gather xm AFTER stream (rows are L2-hot), sorted-index order ----
        {
            const float* xb0 = x + (size_t)(b0 + sbl0) * Lsz;
            const float* xb1 = x + (size_t)(b0 + sbl1) * Lsz;
            float va[8], vb[8];
            #pragma unroll
            for (int c = 0; c < 8; c++) {
                const int gi = s->sortS[c*32 + lane].x;
                va[c] = __ldg(xb0 + gi);
                vb[c] = __ldg(xb1 + gi);
            }
            #pragma unroll
            for (int c = 0; c < 8; c++) {
                const int off = s->sortS[c*32 + lane].y;
                *(float*)(xmBase + off + sbl0*16) = va[c];
                *(float*)(xmBase + off + sbl1*16) = vb[c];
            }
        }
        __syncwarp();

        // ---- phase 1: lsum = relu(xm@W1^T+bl1) + relu(xm@W2^T+bl2) ----
        ull a1a[4], a1b[4], a2a[4], a2b[4];
        #pragma unroll
        for (int i = 0; i < 4; i++) {
            a1a[i] = pk2(bias1, bias1);  a1b[i] = pk2(bias1b, bias1b);
            a2a[i] = pk2(bias2, bias2);  a2b[i] = pk2(bias2b, bias2b);
        }
        #pragma unroll 8
        for (int k = 0; k < 64; k++) {
            const float4 wv = w12G[k][jp];          // LDG.128, L1-resident
            ull w1a = pk2(wv.x, wv.x), w1b = pk2(wv.y, wv.y);
            ull w2a = pk2(wv.z, wv.z), w2b = pk2(wv.w, wv.w);
            ulonglong2 A01 = *(const ulonglong2*)&s->xmPair[k][rp0];
            ulonglong2 A23 = *(const ulonglong2*)&s->xmPair[k][rp0+2];
            fma2(a1a[0], A01.x, w1a); fma2(a1b[0], A01.x, w1b);
            fma2(a2a[0], A01.x, w2a); fma2(a2b[0], A01.x, w2b);
            fma2(a1a[1], A01.y, w1a); fma2(a1b[1], A01.y, w1b);
            fma2(a2a[1], A01.y, w2a); fma2(a2b[1], A01.y, w2b);
            fma2(a1a[2], A23.x, w1a); fma2(a1b[2], A23.x, w1b);
            fma2(a2a[2], A23.x, w2a); fma2(a2b[2], A23.x, w2b);
            fma2(a1a[3], A23.y, w1a); fma2(a1b[3], A23.y, w1b);
            fma2(a2a[3], A23.y, w2a); fma2(a2b[3], A23.y, w2b);
        }
        {   // vectorized STS.128: row j0's 4 pairs, then row j0+1's
            ulonglong2 s0, s1;
            float2 u0 = up2(a1a[0]), v0 = up2(a2a[0]);
            float2 u1 = up2(a1a[1]), v1u = up2(a2a[1]);
            s0.x = pk2(fmaxf(u0.x,0.f)+fmaxf(v0.x,0.f), fmaxf(u0.y,0.f)+fmaxf(v0.y,0.f));
            s0.y = pk2(fmaxf(u1.x,0.f)+fmaxf(v1u.x,0.f), fmaxf(u1.y,0.f)+fmaxf(v1u.y,0.f));
            float2 u2 = up2(a1a[2]), v2u = up2(a2a[2]);
            float2 u3 = up2(a1a[3]), v3 = up2(a2a[3]);
            s1.x = pk2(fmaxf(u2.x,0.f)+fmaxf(v2u.x,0.f), fmaxf(u2.y,0.f)+fmaxf(v2u.y,0.f));
            s1.y = pk2(fmaxf(u3.x,0.f)+fmaxf(v3.x,0.f), fmaxf(u3.y,0.f)+fmaxf(v3.y,0.f));
            *(ulonglong2*)&s->lsumPair[j0][rp0]   = s0;
            *(ulonglong2*)&s->lsumPair[j0][rp0+2] = s1;
            float2 w0 = up2(a1b[0]), x0 = up2(a2b[0]);
            float2 w1 = up2(a1b[1]), x1 = up2(a2b[1]);
            s0.x = pk2(fmaxf(w0.x,0.f)+fmaxf(x0.x,0.f), fmaxf(w0.y,0.f)+fmaxf(x0.y,0.f));
            s0.y = pk2(fmaxf(w1.x,0.f)+fmaxf(x1.x,0.f), fmaxf(w1.y,0.f)+fmaxf(x1.y,0.f));
            float2 w2v = up2(a1b[2]), x2 = up2(a2b[2]);
            float2 w3 = up2(a1b[3]), x3 = up2(a2b[3]);
            s1.x = pk2(fmaxf(w2v.x,0.f)+fmaxf(x2.x,0.f), fmaxf(w2v.y,0.f)+fmaxf(x2.y,0.f));
            s1.y = pk2(fmaxf(w3.x,0.f)+fmaxf(x3.x,0.f), fmaxf(w3.y,0.f)+fmaxf(x3.y,0.f));
            *(ulonglong2*)&s->lsumPair[j0+1][rp0]   = s0;
            *(ulonglong2*)&s->lsumPair[j0+1][rp0+2] = s1;
        }
        __syncwarp();

        // ---- phase 2: A = sigmoid(lsum@Wa^T+ba), xmask=(A+1)*xm, fused conv2 ----
        ull aA0[4], aA1[4];
        #pragma unroll
        for (int i = 0; i < 4; i++) { aA0[i] = pk2(biasA, biasA); aA1[i] = pk2(biasAb, biasAb); }
        #pragma unroll 8
        for (int k = 0; k < 64; k++) {
            const float2 wv = waG[k][jp];           // LDG.64, L1-resident
            ull wa0 = pk2(wv.x, wv.x), wa1 = pk2(wv.y, wv.y);
            ulonglong2 A01 = *(const ulonglong2*)&s->lsumPair[k][rp0];
            ulonglong2 A23 = *(const ulonglong2*)&s->lsumPair[k][rp0+2];
            fma2(aA0[0], A01.x, wa0); fma2(aA1[0], A01.x, wa1);
            fma2(aA0[1], A01.y, wa0); fma2(aA1[1], A01.y, wa1);
            fma2(aA0[2], A23.x, wa0); fma2(aA1[2], A23.x, wa1);
            fma2(aA0[3], A23.y, wa0); fma2(aA1[3], A23.y, wa1);
        }

        // xmask into registers: xmv[i][e][c], i=pair idx, e=elem in pair, c=col (j0+c)
        float xmv[4][2][2];
        #pragma unroll
        for (int i = 0; i < 4; i++) {
            float2 z0 = up2(aA0[i]), z1 = up2(aA1[i]);
            float2 x0 = up2(s->xmPair[j0][rp0+i]);
            float2 x1 = up2(s->xmPair[j0+1][rp0+i]);
            xmv[i][0][0] = (sigmoidf(z0.x)+1.f)*x0.x;
            xmv[i][1][0] = (sigmoidf(z0.y)+1.f)*x0.y;
            xmv[i][0][1] = (sigmoidf(z1.x)+1.f)*x1.x;
            xmv[i][1][1] = (sigmoidf(z1.y)+1.f)*x1.y;
        }
        // column neighbors from adjacent lanes (lane==jp); zero halo at edges
        float lf[4][2], rt[4][2];
        #pragma unroll
        for (int i = 0; i < 4; i++) {
            #pragma unroll
            for (int e = 0; e < 2; e++) {
                float l = __shfl_up_sync(0xffffffffu,  xmv[i][e][1], 1);
                float r = __shfl_down_sync(0xffffffffu, xmv[i][e][0], 1);
                lf[i][e] = (jp == 0)  ? 0.f : l;
                rt[i][e] = (jp == 31) ? 0.f : r;
            }
        }
        // conv2 + double-tanh, straight from registers
        {
            const int sbl = rp0 >> 1;
            #pragma unroll
            for (int oo = 0; oo < 4; oo++) {
                float4 wA = *(const float4*)&s->w2n[oo][0];
                float4 wB = *(const float4*)&s->w2n[oo][4];
                float4 wC = *(const float4*)&s->w2n[oo][8];
                const float wv[12] = {wA.x,wA.y,wA.z,wA.w, wB.x,wB.y,wB.z,wB.w,
                                      wC.x,wC.y,wC.z,wC.w};
                const float bz = s->b2s[oo];
                #pragma unroll
                for (int bb = 0; bb < 2; bb++) {
                    float a0 = bz, a1 = bz;
                    #pragma unroll
                    for (int g = 0; g < 4; g++) {
                        const int i = bb*2 + (g >> 1), e = g & 1;
                        const float xl = lf[i][e], xa = xmv[i][e][0],
                                    xb = xmv[i][e][1], xr = rt[i][e];
                        a0 = fmaf(wv[3*g],   xl, a0);
                        a0 = fmaf(wv[3*g+1], xa, a0);
                        a0 = fmaf(wv[3*g+2], xb, a0);
                        a1 = fmaf(wv[3*g],   xa, a1);
                        a1 = fmaf(wv[3*g+1], xb, a1);
                        a1 = fmaf(wv[3*g+2], xr, a1);
                    }
                    __stcs((float2*)&out_bag[(size_t)(b0 + sbl + bb) * (NGc*GLc) + oo*GLc + j0],
                           make_float2(tanh2(a0), tanh2(a1)));
                }
            }
        }
        __syncwarp();   // order phase-2 xmPair reads before next tile's gather writes
    }
}

extern "C" void kernel_launch(void* const* d_in, const int* in_sizes, int n_in,
                              void* d_out, int out_size)
{
    const float* x   = (const float*)d_in[0];
    const int*   idx = (const int*)  d_in[1];
    const float* v1  = (const float*)d_in[2];
    const float* g1  = (const float*)d_in[3];
    const float* b1  = (const float*)d_in[4];
    const float* v2  = (const float*)d_in[5];
    const float* g2  = (const float*)d_in[6];
    const float* b2  = (const float*)d_in[7];
    const float* W1  = (const float*)d_in[8];
    const float* bl1 = (const float*)d_in[9];
    const float* W2  = (const float*)d_in[10];
    const float* bl2 = (const float*)d_in[11];
    const float* Wa  = (const float*)d_in[12];
    const float* ba  = (const float*)d_in[13];

    prep_kernel<<<8, 256>>>(W1, W2, Wa);
    fused_kernel<<<GRID, NTHREADS>>>(
        x, idx, v1, g1, b1, v2, g2, b2, bl1, bl2, ba, (float*)d_out);
}

// round 16
// speedup vs baseline: 1.4506x; 1.0143x over previous
#include <cuda_runtime.h>
#include <math.h>

#define Bsz 32768
#define Lsz 2048
#define NGc 4
#define GLc 64
#define NTHREADS 256
#define BPT 16                 // batches per tile (= 2 rows per warp)
#define NTILES (Bsz/BPT)       // 2048
#define GRID 444               // 148 SMs x 3 CTAs

typedef unsigned long long ull;

// weight scratch, packed/transposed once by prep_kernel (48KB total — fits L1D; do NOT grow)
__device__ float4 w12G[64][32];   // [k][jp] = {W1[2jp][k],W1[2jp+1][k],W2[2jp][k],W2[2jp+1][k]}
__device__ float2 waG[64][32];    // [k][jp] = {Wa[2jp][k],Wa[2jp+1][k]}

struct __align__(16) Smem {
    ull xmPair[64][34];       // [k][p] = pack(xm of row 2p, row 2p+1); warp w owns p = 4w..4w+3
    ull lsumPair[64][34];     // [k][p] = pack(lsum[2p][k], lsum[2p+1][k]); warp-private likewise
    int   idxS[256];
    int2  sortS[256];         // {gather index (ascending), xmPair byte offset}
    float bl1s[64], bl2s[64], bas[64];
    float w1n[3]; float b1s;
    float w2n[4][12]; float b2s[4];
};

__device__ __forceinline__ ull pk2(float lo, float hi) {
    ull r; asm("mov.b64 %0,{%1,%2};" : "=l"(r) : "f"(lo), "f"(hi)); return r;
}
__device__ __forceinline__ float2 up2(ull v) {
    float2 r; asm("mov.b64 {%0,%1},%2;" : "=f"(r.x), "=f"(r.y) : "l"(v)); return r;
}
__device__ __forceinline__ void fma2(ull& d, ull a, ull b) {
    asm("fma.rn.f32x2 %0,%1,%2,%0;" : "+l"(d) : "l"(a), "l"(b));
}
__device__ __forceinline__ float tanha(float x) {
    float r; asm("tanh.approx.f32 %0,%1;" : "=f"(r) : "f"(x)); return r;
}
__device__ __forceinline__ float tanh2(float x) { return tanha(tanha(x)); }
// sigmoid(z) = 0.5 + 0.5*tanh(z/2): 1 MUFU + 2 FMA (validated rel_err)
__device__ __forceinline__ float sigmoidf(float z) {
    return fmaf(0.5f, tanha(0.5f*z), 0.5f);
}

__global__ void prep_kernel(const float* __restrict__ W1, const float* __restrict__ W2,
                            const float* __restrict__ Wa)
{
    int p = blockIdx.x * blockDim.x + threadIdx.x;
    if (p < 2048) {
        int k = p >> 5, jp = p & 31;
        w12G[k][jp] = make_float4(W1[(2*jp)*64 + k], W1[(2*jp+1)*64 + k],
                                  W2[(2*jp)*64 + k], W2[(2*jp+1)*64 + k]);
        waG[k][jp]  = make_float2(Wa[(2*jp)*64 + k], Wa[(2*jp+1)*64 + k]);
    }
}

// conv1 + double-tanh over TWO full rows as one 16-chunk pipeline, warp-private,
// barrier-free. 4-deep rotating buffer = 3-chunk prefetch; no cold restart at
// the row boundary. Loads DEFAULT-cached (they warm L2 for the gather!);
// stores __stcs (outputs never re-read -> evict-first, preserve L2 for x rows).
__device__ __forceinline__ void stream_rows2(const float4* __restrict__ xr0,
                                             const float4* __restrict__ xr1,
                                             float* __restrict__ so0,
                                             float* __restrict__ so1, int lane,
                                             float cw0, float cw1, float cw2, float cb)
{
    float4 A[4], B[4];
    A[0] = xr0[2*lane];        B[0] = xr0[2*lane+1];
    A[1] = xr0[64 + 2*lane];   B[1] = xr0[64 + 2*lane+1];
    A[2] = xr0[128 + 2*lane];  B[2] = xr0[128 + 2*lane+1];
    float prev_last = 0.f;
    #pragma unroll
    for (int cc = 0; cc < 16; cc++) {
        const int cur = cc & 3, nx = (cc+1) & 3, ld = (cc+3) & 3;
        if (cc < 13) {
            const int tc = cc + 3;
            const float4* base = (tc < 8) ? xr0 : xr1;
            const int off = (tc & 7) * 64;
            A[ld] = base[off + 2*lane];
            B[ld] = base[off + 2*lane + 1];
        }
        const int c = cc & 7;
        float4 ra = A[cur], rb = B[cur];
        float nextfirst = (cc < 15) ? __shfl_sync(0xffffffffu, A[nx].x, 0) : 0.f;
        float em1 = __shfl_up_sync(0xffffffffu,  rb.w, 1);
        float ep8 = __shfl_down_sync(0xffffffffu, ra.x, 1);
        if (lane == 0)  em1 = (c == 0) ? 0.f : prev_last;
        if (lane == 31) ep8 = (c == 7) ? 0.f : nextfirst;
        prev_last = __shfl_sync(0xffffffffu, rb.w, 31);
        float e[10] = {em1, ra.x, ra.y, ra.z, ra.w, rb.x, rb.y, rb.z, rb.w, ep8};
        float r[8];
        #pragma unroll
        for (int q = 0; q < 8; q++)
            r[q] = tanh2(fmaf(cw0, e[q], fmaf(cw1, e[q+1], fmaf(cw2, e[q+2], cb))));
        float* so = (cc < 8) ? so0 : so1;
        float* o = so + c*256 + lane*8;
        __stcs((float4*)o,     make_float4(r[0], r[1], r[2], r[3]));
        __stcs((float4*)(o+4), make_float4(r[4], r[5], r[6], r[7]));
    }
}

__global__ void __launch_bounds__(NTHREADS, 3)
fused_kernel(const float* __restrict__ x, const int* __restrict__ index_all,
             const float* __restrict__ v1, const float* __restrict__ g1, const float* __restrict__ b1,
             const float* __restrict__ v2, const float* __restrict__ g2, const float* __restrict__ b2,
             const float* __restrict__ bl1, const float* __restrict__ bl2,
             const float* __restrict__ ba,
             float* __restrict__ out)
{
    __shared__ Smem sm;
    Smem* s = &sm;
    const int t = threadIdx.x;
    const int lane = t & 31;
    const int w = t >> 5;          // warp id: owns batch rows 2w, 2w+1 of each tile

    // ---------------- init ----------------
    s->idxS[t] = index_all[t];
    if (t < 64) {
        s->bl1s[t] = bl1[t];
        s->bl2s[t] = bl2[t];
        s->bas[t]  = ba[t];
    }
    if (t == 0) {
        float n = sqrtf(v1[0]*v1[0] + v1[1]*v1[1] + v1[2]*v1[2]);
        float gg = g1[0] / n;
        s->w1n[0] = gg*v1[0]; s->w1n[1] = gg*v1[1]; s->w1n[2] = gg*v1[2];
        s->b1s = b1[0];
    }
    if (t < 4) {
        float ss = 0.f;
        #pragma unroll
        for (int m = 0; m < 12; m++) { float vv = v2[t*12+m]; ss += vv*vv; }
        float gg = g2[t] / sqrtf(ss);
        #pragma unroll
        for (int m = 0; m < 12; m++) s->w2n[t][m] = gg * v2[t*12+m];
        s->b2s[t] = b2[t];
    }
    __syncthreads();

    // rank-sort gather indices (stable); precompute scatter byte-offsets
    {
        const int v = s->idxS[t];
        int rank = 0;
        #pragma unroll 8
        for (int j = 0; j < 256; j++) {
            int u = s->idxS[j];
            rank += (u < v) || (u == v && j < t);
        }
        const int k = t & 63, g = t >> 6;
        s->sortS[rank] = make_int2(v, k*272 + (g >> 1)*8 + (g & 1)*4);
    }
    __syncthreads();

    const float cw0 = s->w1n[0], cw1 = s->w1n[1], cw2 = s->w1n[2], cb = s->b1s;
    // MLP mapping: column pair j0=2jp, row-pairs rp0..rp0+3 (8 rows = 2 batches x 4 g)
    const int jp = lane, j0 = 2*jp;
    const int rp0 = w * 4;
    const float bias1 = s->bl1s[j0],   bias1b = s->bl1s[j0+1];
    const float bias2 = s->bl2s[j0],   bias2b = s->bl2s[j0+1];
    const float biasA = s->bas[j0],    biasAb = s->bas[j0+1];

    float* out_bag  = out;
    float* out_site = out + (size_t)Bsz * NGc * GLc;
    char* xmBase = (char*)&s->xmPair[0][0];

    // per-tile state is warp-private -> no CTA barriers in the tile loop
    for (int tile = blockIdx.x; tile < NTILES; tile += GRID) {
        const int b0 = tile * BPT;
        const int sbl0 = 2*w, sbl1 = 2*w + 1;

        // ---- stream 2 warp-private rows (one fused pipeline): conv1 -> x_site ----
        stream_rows2((const float4*)(x + (size_t)(b0 + sbl0) * Lsz),
                     (const float4*)(x + (size_t)(b0 + sbl1) * Lsz),
                     out_site + (size_t)(b0 + sbl0) * Lsz,
                     out_site + (size_t)(b0 + sbl1) * Lsz,
                     lane, cw0, cw1, cw2, cb);

        // ---- gather xm AFTER stream (rows are L2-hot), sorted-index order ----
        {
            const float* xb0 = x + (size_t)(b0 + sbl0) * Lsz;
            const float* xb1 = x + (size_t)(b0 + sbl1) * Lsz;
            float va[8], vb[8];
            #pragma unroll
            for (int c = 0; c < 8; c++) {
                const int gi = s->sortS[c*32 + lane].x;
                va[c] = __ldg(xb0 + gi);
                vb[c] = __ldg(xb1 + gi);
            }
            #pragma unroll
            for (int c = 0; c < 8; c++) {
                const int off = s->sortS[c*32 + lane].y;
                *(float*)(xmBase + off + sbl0*16) = va[c];
                *(float*)(xmBase + off + sbl1*16) = vb[c];
            }
        }
        __syncwarp();

        // ---- phase 1: lsum = relu(xm@W1^T+bl1) + relu(xm@W2^T+bl2) ----
        ull a1a[4], a1b[4], a2a[4], a2b[4];
        #pragma unroll
        for (int i = 0; i < 4; i++) {
            a1a[i] = pk2(bias1, bias1);  a1b[i] = pk2(bias1b, bias1b);
            a2a[i] = pk2(bias2, bias2);  a2b[i] = pk2(bias2b, bias2b);
        }
        #pragma unroll 4
        for (int k = 0; k < 64; k++) {
            const float4 wv = w12G[k][jp];          // LDG.128, L1-resident
            ull w1a = pk2(wv.x, wv.x), w1b = pk2(wv.y, wv.y);
            ull w2a = pk2(wv.z, wv.z), w2b = pk2(wv.w, wv.w);
            ulonglong2 A01 = *(const ulonglong2*)&s->xmPair[k][rp0];
            ulonglong2 A23 = *(const ulonglong2*)&s->xmPair[k][rp0+2];
            fma2(a1a[0], A01.x, w1a); fma2(a1b[0], A01.x, w1b);
            fma2(a2a[0], A01.x, w2a); fma2(a2b[0], A01.x, w2b);
            fma2(a1a[1], A01.y, w1a); fma2(a1b[1], A01.y, w1b);
            fma2(a2a[1], A01.y, w2a); fma2(a2b[1], A01.y, w2b);
            fma2(a1a[2], A23.x, w1a); fma2(a1b[2], A23.x, w1b);
            fma2(a2a[2], A23.x, w2a); fma2(a2b[2], A23.x, w2b);
            fma2(a1a[3], A23.y, w1a); fma2(a1b[3], A23.y, w1b);
            fma2(a2a[3], A23.y, w2a); fma2(a2b[3], A23.y, w2b);
        }
        {   // vectorized STS.128: row j0's 4 pairs, then row j0+1's
            ulonglong2 s0, s1;
            float2 u0 = up2(a1a[0]), v0 = up2(a2a[0]);
            float2 u1 = up2(a1a[1]), v1u = up2(a2a[1]);
            s0.x = pk2(fmaxf(u0.x,0.f)+fmaxf(v0.x,0.f), fmaxf(u0.y,0.f)+fmaxf(v0.y,0.f));
            s0.y = pk2(fmaxf(u1.x,0.f)+fmaxf(v1u.x,0.f), fmaxf(u1.y,0.f)+fmaxf(v1u.y,0.f));
            float2 u2 = up2(a1a[2]), v2u = up2(a2a[2]);
            float2 u3 = up2(a1a[3]), v3 = up2(a2a[3]);
            s1.x = pk2(fmaxf(u2.x,0.f)+fmaxf(v2u.x,0.f), fmaxf(u2.y,0.f)+fmaxf(v2u.y,0.f));
            s1.y = pk2(fmaxf(u3.x,0.f)+fmaxf(v3.x,0.f), fmaxf(u3.y,0.f)+fmaxf(v3.y,0.f));
            *(ulonglong2*)&s->lsumPair[j0][rp0]   = s0;
            *(ulonglong2*)&s->lsumPair[j0][rp0+2] = s1;
            float2 w0 = up2(a1b[0]), x0 = up2(a2b[0]);
            float2 w1 = up2(a1b[1]), x1 = up2(a2b[1]);
            s0.x = pk2(fmaxf(w0.x,0.f)+fmaxf(x0.x,0.f), fmaxf(w0.y,0.f)+fmaxf(x0.y,0.f));
            s0.y = pk2(fmaxf(w1.x,0.f)+fmaxf(x1.x,0.f), fmaxf(w1.y,0.f)+fmaxf(x1.y,0.f));
            float2 w2v = up2(a1b[2]), x2 = up2(a2b[2]);
            float2 w3 = up2(a1b[3]), x3 = up2(a2b[3]);
            s1.x = pk2(fmaxf(w2v.x,0.f)+fmaxf(x2.x,0.f), fmaxf(w2v.y,0.f)+fmaxf(x2.y,0.f));
            s1.y = pk2(fmaxf(w3.x,0.f)+fmaxf(x3.x,0.f), fmaxf(w3.y,0.f)+fmaxf(x3.y,0.f));
            *(ulonglong2*)&s->lsumPair[j0+1][rp0]   = s0;
            *(ulonglong2*)&s->lsumPair[j0+1][rp0+2] = s1;
        }
        __syncwarp();

        // ---- phase 2: A = sigmoid(lsum@Wa^T+ba), xmask=(A+1)*xm, fused conv2 ----
        ull aA0[4], aA1[4];
        #pragma unroll
        for (int i = 0; i < 4; i++) { aA0[i] = pk2(biasA, biasA); aA1[i] = pk2(biasAb, biasAb); }
        #pragma unroll 4
        for (int k = 0; k < 64; k++) {
            const float2 wv = waG[k][jp];           // LDG.64, L1-resident
            ull wa0 = pk2(wv.x, wv.x), wa1 = pk2(wv.y, wv.y);
            ulonglong2 A01 = *(const ulonglong2*)&s->lsumPair[k][rp0];
            ulonglong2 A23 = *(const ulonglong2*)&s->lsumPair[k][rp0+2];
            fma2(aA0[0], A01.x, wa0); fma2(aA1[0], A01.x, wa1);
            fma2(aA0[1], A01.y, wa0); fma2(aA1[1], A01.y, wa1);
            fma2(aA0[2], A23.x, wa0); fma2(aA1[2], A23.x, wa1);
            fma2(aA0[3], A23.y, wa0); fma2(aA1[3], A23.y, wa1);
        }

        // xmask into registers: xmv[i][e][c], i=pair idx, e=elem in pair, c=col (j0+c)
        float xmv[4][2][2];
        #pragma unroll
        for (int i = 0; i < 4; i++) {
            float2 z0 = up2(aA0[i]), z1 = up2(aA1[i]);
            float2 x0 = up2(s->xmPair[j0][rp0+i]);
            float2 x1 = up2(s->xmPair[j0+1][rp0+i]);
            xmv[i][0][0] = (sigmoidf(z0.x)+1.f)*x0.x;
            xmv[i][1][0] = (sigmoidf(z0.y)+1.f)*x0.y;
            xmv[i][0][1] = (sigmoidf(z1.x)+1.f)*x1.x;
            xmv[i][1][1] = (sigmoidf(z1.y)+1.f)*x1.y;
        }
        // column neighbors from adjacent lanes (lane==jp); zero halo at edges
        float lf[4][2], rt[4][2];
        #pragma unroll
        for (int i = 0; i < 4; i++) {
            #pragma unroll
            for (int e = 0; e < 2; e++) {
                float l = __shfl_up_sync(0xffffffffu,  xmv[i][e][1], 1);
                float r = __shfl_down_sync(0xffffffffu, xmv[i][e][0], 1);
                lf[i][e] = (jp == 0)  ? 0.f : l;
                rt[i][e] = (jp == 31) ? 0.f : r;
            }
        }
        // conv2 + double-tanh, straight from registers
        {
            const int sbl = rp0 >> 1;
            #pragma unroll
            for (int oo = 0; oo < 4; oo++) {
                float4 wA = *(const float4*)&s->w2n[oo][0];
                float4 wB = *(const float4*)&s->w2n[oo][4];
                float4 wC = *(const float4*)&s->w2n[oo][8];
                const float wv[12] = {wA.x,wA.y,wA.z,wA.w, wB.x,wB.y,wB.z,wB.w,
                                      wC.x,wC.y,wC.z,wC.w};
                const float bz = s->b2s[oo];
                #pragma unroll
                for (int bb = 0; bb < 2; bb++) {
                    float a0 = bz, a1 = bz;
                    #pragma unroll
                    for (int g = 0; g < 4; g++) {
                        const int i = bb*2 + (g >> 1), e = g & 1;
                        const float xl = lf[i][e], xa = xmv[i][e][0],
                                    xb = xmv[i][e][1], xr = rt[i][e];
                        a0 = fmaf(wv[3*g],   xl, a0);
                        a0 = fmaf(wv[3*g+1], xa, a0);
                        a0 = fmaf(wv[3*g+2], xb, a0);
                        a1 = fmaf(wv[3*g],   xa, a1);
                        a1 = fmaf(wv[3*g+1], xb, a1);
                        a1 = fmaf(wv[3*g+2], xr, a1);
                    }
                    __stcs((float2*)&out_bag[(size_t)(b0 + sbl + bb) * (NGc*GLc) + oo*GLc + j0],
                           make_float2(tanh2(a0), tanh2(a1)));
                }
            }
        }
        __syncwarp();   // order phase-2 xmPair reads before next tile's gather writes
    }
}

extern "C" void kernel_launch(void* const* d_in, const int* in_sizes, int n_in,
                              void* d_out, int out_size)
{
    const float* x   = (const float*)d_in[0];
    const int*   idx = (const int*)  d_in[1];
    const float* v1  = (const float*)d_in[2];
    const float* g1  = (const float*)d_in[3];
    const float* b1  = (const float*)d_in[4];
    const float* v2  = (const float*)d_in[5];
    const float* g2  = (const float*)d_in[6];
    const float* b2  = (const float*)d_in[7];
    const float* W1  = (const float*)d_in[8];
    const float* bl1 = (const float*)d_in[9];
    const float* W2  = (const float*)d_in[10];
    const float* bl2 = (const float*)d_in[11];
    const float* Wa  = (const float*)d_in[12];
    const float* ba  = (const float*)d_in[13];

    prep_kernel<<<8, 256>>>(W1, W2, Wa);
    fused_kernel<<<GRID, NTHREADS>>>(
        x, idx, v1, g1, b1, v2, g2, b2, bl1, bl2, ba, (float*)d_out);
}